// round 15
// baseline (speedup 1.0000x reference)
#include <cuda_runtime.h>
#include <cuda_bf16.h>
#include <math.h>

// ---------------- problem constants ----------------
#define BATCH      32
#define T_SAMPLES  480000
#define FRAME_LEN  400
#define FRAME_SHIFT 160
#define NFFT       512
#define NK         257
#define NMEL       80
#define NFRAMES    2998
#define NPAIRS     (NFRAMES/2)       // 1499
#define M_TOTAL    (BATCH*NFRAMES)   // 95936
#define SCALE      32768.0f
#define PREEMPH    0.97f
#define EPS_F      1.1920928955078125e-07f
#define MAXSUP     24

// ---------------- scratch ----------------
__device__ float g_mean [BATCH * NMEL];
__device__ int   g_klo  [NMEL];
__device__ int   g_kcnt [NMEL];
__device__ float g_wpack[MAXSUP * NMEL];

// ================= f32x2 packed-math helpers =================
typedef unsigned long long f2_t;

__device__ __forceinline__ f2_t f2_pack(float lo, float hi) {
    f2_t r; asm("mov.b64 %0,{%1,%2};" : "=l"(r) : "f"(lo), "f"(hi)); return r;
}
__device__ __forceinline__ void f2_unpack(f2_t a, float& lo, float& hi) {
    asm("mov.b64 {%0,%1},%2;" : "=f"(lo), "=f"(hi) : "l"(a));
}
__device__ __forceinline__ f2_t f2add(f2_t a, f2_t b){ f2_t d; asm("add.rn.f32x2 %0,%1,%2;" : "=l"(d) : "l"(a), "l"(b)); return d; }
__device__ __forceinline__ f2_t f2sub(f2_t a, f2_t b){ f2_t d; asm("sub.rn.f32x2 %0,%1,%2;" : "=l"(d) : "l"(a), "l"(b)); return d; }
__device__ __forceinline__ f2_t f2mul(f2_t a, f2_t b){ f2_t d; asm("mul.rn.f32x2 %0,%1,%2;" : "=l"(d) : "l"(a), "l"(b)); return d; }
__device__ __forceinline__ f2_t f2fma(f2_t a, f2_t b, f2_t c){ f2_t d; asm("fma.rn.f32x2 %0,%1,%2,%3;" : "=l"(d) : "l"(a), "l"(b), "l"(c)); return d; }

// ================= init: mel support bounds + packed weights =================
__global__ void k_init(const float* __restrict__ melf)
{
    __shared__ int sklo[NMEL];
    const int t = threadIdx.x;
    if (t < NMEL) {
        double mel_lo = 1127.0 * log(1.0 + 20.0 / 700.0);
        double mel_hi = 1127.0 * log(1.0 + 8000.0 / 700.0);
        double delta  = (mel_hi - mel_lo) / (double)(NMEL + 1);
        double left   = mel_lo + t * delta;
        double right  = left + 2.0 * delta;
        double fl     = 700.0 * (exp(left  / 1127.0) - 1.0);
        double fr     = 700.0 * (exp(right / 1127.0) - 1.0);
        int klo = (int)floor(fl / 31.25) - 1;
        if (klo < 0) klo = 0;
        int khi = (int)ceil(fr / 31.25) + 1;
        if (khi > 256) khi = 256;
        int cnt = khi - klo + 1;
        if (cnt > MAXSUP) cnt = MAXSUP;
        sklo[t] = klo;
        if (blockIdx.x == 0) {
            g_klo[t]  = klo;
            g_kcnt[t] = cnt;
        }
    }
    __syncthreads();
    for (int idx = blockIdx.x * blockDim.x + t; idx < MAXSUP * NMEL;
         idx += gridDim.x * blockDim.x) {
        int j = idx / NMEL, m = idx % NMEL;
        int k = sklo[m] + j;
        g_wpack[j * NMEL + m] = (k <= 256) ? melf[(size_t)k * NMEL + m] : 0.f;
    }
}

// 8-point DFT on f32x2-packed registers
__device__ __forceinline__ void fft8p(f2_t* r, f2_t* q, f2_t Cp)
{
    f2_t t0r=f2add(r[0],r[4]), t0i=f2add(q[0],q[4]);
    f2_t t1r=f2sub(r[0],r[4]), t1i=f2sub(q[0],q[4]);
    f2_t t2r=f2add(r[2],r[6]), t2i=f2add(q[2],q[6]);
    f2_t t3r=f2sub(r[2],r[6]), t3i=f2sub(q[2],q[6]);
    f2_t e0r=f2add(t0r,t2r), e0i=f2add(t0i,t2i);
    f2_t e2r=f2sub(t0r,t2r), e2i=f2sub(t0i,t2i);
    f2_t e1r=f2add(t1r,t3i), e1i=f2sub(t1i,t3r);
    f2_t e3r=f2sub(t1r,t3i), e3i=f2add(t1i,t3r);

    f2_t s0r=f2add(r[1],r[5]), s0i=f2add(q[1],q[5]);
    f2_t s1r=f2sub(r[1],r[5]), s1i=f2sub(q[1],q[5]);
    f2_t s2r=f2add(r[3],r[7]), s2i=f2add(q[3],q[7]);
    f2_t s3r=f2sub(r[3],r[7]), s3i=f2sub(q[3],q[7]);
    f2_t o0r=f2add(s0r,s2r), o0i=f2add(s0i,s2i);
    f2_t o2r=f2sub(s0r,s2r), o2i=f2sub(s0i,s2i);
    f2_t o1r=f2add(s1r,s3i), o1i=f2sub(s1i,s3r);
    f2_t o3r=f2sub(s1r,s3i), o3i=f2add(s1i,s3r);

    f2_t u1r=f2mul(f2add(o1r,o1i),Cp);
    f2_t u1i=f2mul(f2sub(o1i,o1r),Cp);
    f2_t u3r=f2mul(f2sub(o3i,o3r),Cp);
    f2_t ct3=f2mul(f2add(o3r,o3i),Cp);   // u3i = -ct3

    r[0]=f2add(e0r,o0r); q[0]=f2add(e0i,o0i);
    r[4]=f2sub(e0r,o0r); q[4]=f2sub(e0i,o0i);
    r[1]=f2add(e1r,u1r); q[1]=f2add(e1i,u1i);
    r[5]=f2sub(e1r,u1r); q[5]=f2sub(e1i,u1i);
    r[2]=f2add(e2r,o2i); q[2]=f2sub(e2i,o2r);
    r[6]=f2sub(e2r,o2i); q[6]=f2add(e2i,o2r);
    r[3]=f2add(e3r,u3r); q[3]=f2sub(e3i,ct3);
    r[7]=f2sub(e3r,u3r); q[7]=f2add(e3i,ct3);
}

// =====================================================================
// Fused kernel: 2 groups x 64 threads; TWO frame-pairs per group packed
// in f32x2. Register raw loads + shuffle preemph + smem twiddle table.
// =====================================================================
__global__ __launch_bounds__(128)
void k_fused(const float* __restrict__ wav,
             const float* __restrict__ window,
             const float* __restrict__ dcos,
             const float* __restrict__ dsin,
             float* __restrict__ out)
{
    __shared__ ulonglong2 cx[2][640];    // [gid]: {re-packed, im-packed}
    __shared__ f2_t pw2[2][2][264];      // [gid][fr][k] power packed over pairs
    __shared__ f2_t red[2][2][2];        // [gid][comp][warpInGroup] packed sums
    __shared__ f2_t sbnd[2][2][2][8];    // [gid][warpEnd][comp][m] boundary raw
    __shared__ float2 stw[512];          // block-shared twiddle table {cos,sin}

    const int tid = threadIdx.x;
    const int gid = tid >> 6;
    const int lt  = tid & 63;
    const int wg  = (tid >> 5) & 1;
    const int b   = blockIdx.y;

    const int paBase = 4 * blockIdx.x + 2 * gid;
    bool val[2]; int pc[2];
    #pragma unroll
    for (int p = 0; p < 2; p++) {
        int pa = paBase + p;
        val[p] = (pa < NPAIRS);
        pc[p]  = val[p] ? pa : (NPAIRS - 1);
    }

    // ---- fill twiddle table (coalesced; covered by barrier B1) ----
    #pragma unroll
    for (int a = tid; a < 512; a += 128)
        stw[a] = make_float2(__ldg(dcos + 512 + a), __ldg(dsin + 512 + a));

    // ---- register-resident raw loads (packed over pairs) + packed sums ----
    const float* xA = wav + (size_t)b * T_SAMPLES + (size_t)(2 * pc[0]) * FRAME_SHIFT;
    const float* xB = wav + (size_t)b * T_SAMPLES + (size_t)(2 * pc[1]) * FRAME_SHIFT;
    f2_t rawF0[8], rawF1[8];
    f2_t psum0 = 0ULL, psum1 = 0ULL;
    #pragma unroll
    for (int m = 0; m < 8; m++) {
        int i = lt + 64 * m;
        float a0 = 0.f, a1 = 0.f, b0 = 0.f, b1 = 0.f;
        if (i < FRAME_LEN) {
            a0 = xA[i] * SCALE;               b0 = xA[i + FRAME_SHIFT] * SCALE;
            a1 = xB[i] * SCALE;               b1 = xB[i + FRAME_SHIFT] * SCALE;
        }
        rawF0[m] = f2_pack(a0, a1);
        rawF1[m] = f2_pack(b0, b1);
        psum0 = f2add(psum0, rawF0[m]);
        psum1 = f2add(psum1, rawF1[m]);
    }
    #pragma unroll
    for (int off = 16; off > 0; off >>= 1) {
        psum0 = f2add(psum0, __shfl_xor_sync(0xffffffffu, psum0, off));
        psum1 = f2add(psum1, __shfl_xor_sync(0xffffffffu, psum1, off));
    }
    if ((lt & 31) == 0) {
        red[gid][0][wg] = psum0;
        red[gid][1][wg] = psum1;
    }
    // boundary raw values for cross-warp preemph
    if (lt == 31 || lt == 63) {
        int e = lt >> 5;
        #pragma unroll
        for (int m = 0; m < 8; m++) {
            sbnd[gid][e][0][m] = rawF0[m];
            sbnd[gid][e][1][m] = rawF1[m];
        }
    }
    __syncthreads();                                   // B1

    const float mcoef = 1.0f - PREEMPH;
    const f2_t invN  = f2_pack(1.0f / FRAME_LEN, 1.0f / FRAME_LEN);
    const f2_t mco   = f2_pack(mcoef, mcoef);
    const f2_t meanF0 = f2mul(f2add(red[gid][0][0], red[gid][0][1]), invN);
    const f2_t meanF1 = f2mul(f2add(red[gid][1][0], red[gid][1][1]), invN);
    const f2_t m03F0 = f2mul(meanF0, mco);
    const f2_t m03F1 = f2mul(meanF1, mco);
    const f2_t negP  = f2_pack(-PREEMPH, -PREEMPH);
    const f2_t Cp    = f2_pack(0.70710678118654752440f, 0.70710678118654752440f);

    // ---- preemph + window into packed stage-1 registers ----
    f2_t XR[8], XI[8];
    #pragma unroll
    for (int m = 0; m < 8; m++) {
        f2_t up0 = __shfl_up_sync(0xffffffffu, rawF0[m], 1);
        f2_t up1 = __shfl_up_sync(0xffffffffu, rawF1[m], 1);
        if (lt == 0)  { up0 = (m == 0) ? rawF0[0] : sbnd[gid][1][0][m - 1];
                        up1 = (m == 0) ? rawF1[0] : sbnd[gid][1][1][m - 1]; }
        if (lt == 32) { up0 = sbnd[gid][0][0][m];
                        up1 = sbnd[gid][0][1][m]; }
        int i = lt + 64 * m;
        if (i < FRAME_LEN) {
            float w = __ldg(window + i);
            f2_t Wp = f2_pack(w, w);
            XR[m] = f2mul(f2sub(f2fma(up0, negP, rawF0[m]), m03F0), Wp);
            XI[m] = f2mul(f2sub(f2fma(up1, negP, rawF1[m]), m03F1), Wp);
        } else {
            XR[m] = 0ULL; XI[m] = 0ULL;
        }
    }

    // ---- stage 1: twiddle W512^{lt*j} from smem table ----
    {
        f2_t cp[8], sp[8];
        #pragma unroll
        for (int j = 1; j < 8; j++) {
            float2 t = stw[(lt * j) & 511];
            cp[j] = f2_pack(t.x, t.x); sp[j] = f2_pack(t.y, t.y);
        }
        fft8p(XR, XI, Cp);
        #pragma unroll
        for (int j = 1; j < 8; j++) {
            f2_t t1 = f2mul(XI[j], sp[j]);
            f2_t t2 = f2mul(XR[j], sp[j]);
            f2_t rr = f2fma(XR[j], cp[j], t1);
            XI[j] = f2sub(f2mul(XI[j], cp[j]), t2);
            XR[j] = rr;
        }
    }

    // ---- exchange 1: cx[72j + lt] (first touch of cx; no barrier needed) ----
    #pragma unroll
    for (int j = 0; j < 8; j++)
        cx[gid][72 * j + lt] = make_ulonglong2(XR[j], XI[j]);
    __syncthreads();                                   // B3
    const int J = lt >> 3, v = lt & 7;
    #pragma unroll
    for (int m = 0; m < 8; m++) {
        ulonglong2 z = cx[gid][72 * J + v + 8 * m];
        XR[m] = z.x; XI[m] = z.y;
    }

    // ---- stage 2: twiddle W64^{v*i} = W512^{8vi} from smem table ----
    {
        f2_t cp[8], sp[8];
        #pragma unroll
        for (int i = 1; i < 8; i++) {
            float2 t = stw[(8 * v * i) & 511];
            cp[i] = f2_pack(t.x, t.x); sp[i] = f2_pack(t.y, t.y);
        }
        fft8p(XR, XI, Cp);
        #pragma unroll
        for (int i = 1; i < 8; i++) {
            f2_t t1 = f2mul(XI[i], sp[i]);
            f2_t t2 = f2mul(XR[i], sp[i]);
            f2_t rr = f2fma(XR[i], cp[i], t1);
            XI[i] = f2sub(f2mul(XI[i], cp[i]), t2);
            XR[i] = rr;
        }
    }

    // ---- exchange 2: cx[80J + 9i + v] ----
    __syncthreads();                                   // B4
    #pragma unroll
    for (int i = 0; i < 8; i++)
        cx[gid][80 * J + 9 * i + v] = make_ulonglong2(XR[i], XI[i]);
    __syncthreads();                                   // B5
    const int I = v;
    #pragma unroll
    for (int m = 0; m < 8; m++) {
        ulonglong2 z = cx[gid][80 * J + 9 * I + m];
        XR[m] = z.x; XI[m] = z.y;
    }

    // ---- stage 3 (no twiddle). Result: X[64s + 8I + J] ----
    fft8p(XR, XI, Cp);

    // ---- natural-order store at swizzled address 72s + 9I + J ----
    __syncthreads();                                   // B6
    #pragma unroll
    for (int s = 0; s < 8; s++)
        cx[gid][72 * s + 9 * I + J] = make_ulonglong2(XR[s], XI[s]);
    __syncthreads();                                   // B7

    // ---- conjugate-symmetry split + power (packed) ----
    {
        const f2_t halfp = f2_pack(0.5f, 0.5f);
        for (int k = lt; k < NK; k += 64) {
            int n = (NFFT - k) & (NFFT - 1);
            int ak = 72 * (k >> 6) + 9 * ((k >> 3) & 7) + (k & 7);
            int an = 72 * (n >> 6) + 9 * ((n >> 3) & 7) + (n & 7);
            ulonglong2 zk = cx[gid][ak];
            ulonglong2 zn = cx[gid][an];
            f2_t Xr = f2mul(f2add(zk.x, zn.x), halfp);
            f2_t Xi = f2mul(f2sub(zk.y, zn.y), halfp);
            f2_t Yr = f2mul(f2add(zk.y, zn.y), halfp);
            f2_t Yi = f2mul(f2sub(zn.x, zk.x), halfp);
            pw2[gid][0][k] = f2fma(Xr, Xr, f2mul(Xi, Xi));
            pw2[gid][1][k] = f2fma(Yr, Yr, f2mul(Yi, Yi));
        }
    }
    __syncthreads();                                   // B8

    // ---- packed mel + log (exact support width) ----
    for (int idx = lt; idx < 2 * NMEL; idx += 64) {
        const int fr = (idx < NMEL) ? 0 : 1;
        const int m  = idx - fr * NMEL;
        const int klo = __ldg(&g_klo[m]);
        const int cnt = __ldg(&g_kcnt[m]);

        const f2_t* pk = &pw2[gid][fr][klo];
        f2_t acc = 0ULL;
        for (int j = 0; j < cnt; j++) {
            float w = __ldg(&g_wpack[j * NMEL + m]);
            acc = f2fma(pk[j], f2_pack(w, w), acc);
        }
        float a0, a1;
        f2_unpack(acc, a0, a1);

        if (val[0])
            out[(size_t)(b * NFRAMES + 2 * pc[0] + fr) * NMEL + m] = __logf(fmaxf(a0, EPS_F));
        if (val[1])
            out[(size_t)(b * NFRAMES + 2 * pc[1] + fr) * NMEL + m] = __logf(fmaxf(a1, EPS_F));
    }
}

// ================= CMN: one block per batch computes means =================
__global__ __launch_bounds__(1024)
void k_cmn_mean2(const float* __restrict__ out)
{
    __shared__ float4 sm[1020];
    const int b   = blockIdx.x;
    const int tid = threadIdx.x;
    const int lane = tid % 20;
    const int s    = tid / 20;

    float4 acc = make_float4(0.f, 0.f, 0.f, 0.f);
    if (s < 51) {
        for (int f = s; f < NFRAMES; f += 51) {
            float4 vv = *(const float4*)(out + ((size_t)b * NFRAMES + f) * NMEL + lane * 4);
            acc.x += vv.x; acc.y += vv.y; acc.z += vv.z; acc.w += vv.w;
        }
        sm[s * 20 + lane] = acc;
    }
    __syncthreads();
    #pragma unroll
    for (int h = 32; h > 0; h >>= 1) {
        if (s < h && s + h < 51) {
            float4 o_ = sm[(s + h) * 20 + lane];
            float4 m_ = sm[s * 20 + lane];
            m_.x += o_.x; m_.y += o_.y; m_.z += o_.z; m_.w += o_.w;
            sm[s * 20 + lane] = m_;
        }
        __syncthreads();
    }
    if (tid < 20) {
        float4 t = sm[tid];
        const float inv = 1.0f / NFRAMES;
        t.x *= inv; t.y *= inv; t.z *= inv; t.w *= inv;
        *(float4*)(g_mean + b * NMEL + tid * 4) = t;
    }
}

// subtract: 2-D grid, batch in blockIdx.y (no 64-bit div)
__global__ void k_cmn_sub(float* __restrict__ out)
{
    const int per_b = NFRAMES * (NMEL / 4);      // 59960 float4 per batch
    int i = blockIdx.x * blockDim.x + threadIdx.x;
    if (i >= per_b) return;
    const int b = blockIdx.y;
    int m4 = i % (NMEL / 4);
    float4 mu = *(const float4*)(g_mean + b * NMEL + m4 * 4);
    float4* ptr = (float4*)(out + (size_t)b * NFRAMES * NMEL) + i;
    float4 vv = *ptr;
    vv.x -= mu.x; vv.y -= mu.y; vv.z -= mu.z; vv.w -= mu.w;
    *ptr = vv;
}

// ================= launch =================
extern "C" void kernel_launch(void* const* d_in, const int* in_sizes, int n_in,
                              void* d_out, int out_size)
{
    const float* wav    = (const float*)d_in[0];
    const float* window = (const float*)d_in[1];
    const float* melf   = (const float*)d_in[2];
    const float* dcos   = (const float*)d_in[3];
    const float* dsin   = (const float*)d_in[4];
    float* out = (float*)d_out;

    k_init<<<8, 256>>>(melf);
    k_fused<<<dim3((NPAIRS + 3) / 4, BATCH), 128>>>(wav, window, dcos, dsin, out);
    k_cmn_mean2<<<BATCH, 1024>>>(out);
    {
        int per_b = NFRAMES * (NMEL / 4);
        k_cmn_sub<<<dim3((per_b + 255) / 256, BATCH), 256>>>(out);
    }
}

// round 16
// speedup vs baseline: 1.1157x; 1.1157x over previous
#include <cuda_runtime.h>
#include <cuda_bf16.h>
#include <math.h>

// ---------------- problem constants ----------------
#define BATCH      32
#define T_SAMPLES  480000
#define FRAME_LEN  400
#define FRAME_SHIFT 160
#define NFFT       512
#define NK         257
#define NMEL       80
#define NFRAMES    2998
#define NPAIRS     (NFRAMES/2)       // 1499
#define M_TOTAL    (BATCH*NFRAMES)   // 95936
#define SCALE      32768.0f
#define PREEMPH    0.97f
#define EPS_F      1.1920928955078125e-07f
#define MAXSUP     24

// ---------------- scratch ----------------
__device__ float g_mean [BATCH * NMEL];
__device__ int   g_klo  [NMEL];
__device__ int   g_kcnt [NMEL];
__device__ float g_wpack[MAXSUP * NMEL];

// ================= f32x2 packed-math helpers =================
typedef unsigned long long f2_t;

__device__ __forceinline__ f2_t f2_pack(float lo, float hi) {
    f2_t r; asm("mov.b64 %0,{%1,%2};" : "=l"(r) : "f"(lo), "f"(hi)); return r;
}
__device__ __forceinline__ void f2_unpack(f2_t a, float& lo, float& hi) {
    asm("mov.b64 {%0,%1},%2;" : "=f"(lo), "=f"(hi) : "l"(a));
}
__device__ __forceinline__ f2_t f2add(f2_t a, f2_t b){ f2_t d; asm("add.rn.f32x2 %0,%1,%2;" : "=l"(d) : "l"(a), "l"(b)); return d; }
__device__ __forceinline__ f2_t f2sub(f2_t a, f2_t b){ f2_t d; asm("sub.rn.f32x2 %0,%1,%2;" : "=l"(d) : "l"(a), "l"(b)); return d; }
__device__ __forceinline__ f2_t f2mul(f2_t a, f2_t b){ f2_t d; asm("mul.rn.f32x2 %0,%1,%2;" : "=l"(d) : "l"(a), "l"(b)); return d; }
__device__ __forceinline__ f2_t f2fma(f2_t a, f2_t b, f2_t c){ f2_t d; asm("fma.rn.f32x2 %0,%1,%2,%3;" : "=l"(d) : "l"(a), "l"(b), "l"(c)); return d; }

// ================= init: mel support bounds + packed weights =================
__global__ void k_init(const float* __restrict__ melf)
{
    __shared__ int sklo[NMEL];
    const int t = threadIdx.x;
    if (t < NMEL) {
        double mel_lo = 1127.0 * log(1.0 + 20.0 / 700.0);
        double mel_hi = 1127.0 * log(1.0 + 8000.0 / 700.0);
        double delta  = (mel_hi - mel_lo) / (double)(NMEL + 1);
        double left   = mel_lo + t * delta;
        double right  = left + 2.0 * delta;
        double fl     = 700.0 * (exp(left  / 1127.0) - 1.0);
        double fr     = 700.0 * (exp(right / 1127.0) - 1.0);
        int klo = (int)floor(fl / 31.25) - 1;
        if (klo < 0) klo = 0;
        int khi = (int)ceil(fr / 31.25) + 1;
        if (khi > 256) khi = 256;
        int cnt = khi - klo + 1;
        if (cnt > MAXSUP) cnt = MAXSUP;
        sklo[t] = klo;
        if (blockIdx.x == 0) {
            g_klo[t]  = klo;
            g_kcnt[t] = cnt;
        }
    }
    __syncthreads();
    for (int idx = blockIdx.x * blockDim.x + t; idx < MAXSUP * NMEL;
         idx += gridDim.x * blockDim.x) {
        int j = idx / NMEL, m = idx % NMEL;
        int k = sklo[m] + j;
        g_wpack[j * NMEL + m] = (k <= 256) ? melf[(size_t)k * NMEL + m] : 0.f;
    }
}

// 8-point DFT on f32x2-packed registers
__device__ __forceinline__ void fft8p(f2_t* r, f2_t* q, f2_t Cp)
{
    f2_t t0r=f2add(r[0],r[4]), t0i=f2add(q[0],q[4]);
    f2_t t1r=f2sub(r[0],r[4]), t1i=f2sub(q[0],q[4]);
    f2_t t2r=f2add(r[2],r[6]), t2i=f2add(q[2],q[6]);
    f2_t t3r=f2sub(r[2],r[6]), t3i=f2sub(q[2],q[6]);
    f2_t e0r=f2add(t0r,t2r), e0i=f2add(t0i,t2i);
    f2_t e2r=f2sub(t0r,t2r), e2i=f2sub(t0i,t2i);
    f2_t e1r=f2add(t1r,t3i), e1i=f2sub(t1i,t3r);
    f2_t e3r=f2sub(t1r,t3i), e3i=f2add(t1i,t3r);

    f2_t s0r=f2add(r[1],r[5]), s0i=f2add(q[1],q[5]);
    f2_t s1r=f2sub(r[1],r[5]), s1i=f2sub(q[1],q[5]);
    f2_t s2r=f2add(r[3],r[7]), s2i=f2add(q[3],q[7]);
    f2_t s3r=f2sub(r[3],r[7]), s3i=f2sub(q[3],q[7]);
    f2_t o0r=f2add(s0r,s2r), o0i=f2add(s0i,s2i);
    f2_t o2r=f2sub(s0r,s2r), o2i=f2sub(s0i,s2i);
    f2_t o1r=f2add(s1r,s3i), o1i=f2sub(s1i,s3r);
    f2_t o3r=f2sub(s1r,s3i), o3i=f2add(s1i,s3r);

    f2_t u1r=f2mul(f2add(o1r,o1i),Cp);
    f2_t u1i=f2mul(f2sub(o1i,o1r),Cp);
    f2_t u3r=f2mul(f2sub(o3i,o3r),Cp);
    f2_t ct3=f2mul(f2add(o3r,o3i),Cp);   // u3i = -ct3

    r[0]=f2add(e0r,o0r); q[0]=f2add(e0i,o0i);
    r[4]=f2sub(e0r,o0r); q[4]=f2sub(e0i,o0i);
    r[1]=f2add(e1r,u1r); q[1]=f2add(e1i,u1i);
    r[5]=f2sub(e1r,u1r); q[5]=f2sub(e1i,u1i);
    r[2]=f2add(e2r,o2i); q[2]=f2sub(e2i,o2r);
    r[6]=f2sub(e2r,o2i); q[6]=f2add(e2i,o2r);
    r[3]=f2add(e3r,u3r); q[3]=f2sub(e3i,ct3);
    r[7]=f2sub(e3r,u3r); q[7]=f2add(e3i,ct3);
}

// =====================================================================
// Fused kernel: 2 groups x 64 threads; TWO frame-pairs per group packed
// in f32x2. Register-resident raw loads + shuffle preemph (no raw smem).
// =====================================================================
__global__ __launch_bounds__(128)
void k_fused(const float* __restrict__ wav,
             const float* __restrict__ window,
             const float* __restrict__ dcos,
             const float* __restrict__ dsin,
             float* __restrict__ out)
{
    __shared__ ulonglong2 cx[2][640];    // [gid]: {re-packed, im-packed}
    __shared__ f2_t pw2[2][2][264];      // [gid][fr][k] power packed over pairs
    __shared__ f2_t red[2][2][2];        // [gid][comp][warpInGroup] packed sums
    __shared__ f2_t sbnd[2][2][2][8];    // [gid][warpEnd][comp][m] boundary raw

    const int tid = threadIdx.x;
    const int gid = tid >> 6;
    const int lt  = tid & 63;
    const int wg  = (tid >> 5) & 1;
    const int b   = blockIdx.y;

    const int paBase = 4 * blockIdx.x + 2 * gid;
    bool val[2]; int pc[2];
    #pragma unroll
    for (int p = 0; p < 2; p++) {
        int pa = paBase + p;
        val[p] = (pa < NPAIRS);
        pc[p]  = val[p] ? pa : (NPAIRS - 1);
    }

    // ---- register-resident raw loads (packed over pairs) + packed sums ----
    const float* xA = wav + (size_t)b * T_SAMPLES + (size_t)(2 * pc[0]) * FRAME_SHIFT;
    const float* xB = wav + (size_t)b * T_SAMPLES + (size_t)(2 * pc[1]) * FRAME_SHIFT;
    f2_t rawF0[8], rawF1[8];
    f2_t psum0 = 0ULL, psum1 = 0ULL;
    #pragma unroll
    for (int m = 0; m < 8; m++) {
        int i = lt + 64 * m;
        float a0 = 0.f, a1 = 0.f, b0 = 0.f, b1 = 0.f;
        if (i < FRAME_LEN) {
            a0 = xA[i] * SCALE;               b0 = xA[i + FRAME_SHIFT] * SCALE;
            a1 = xB[i] * SCALE;               b1 = xB[i + FRAME_SHIFT] * SCALE;
        }
        rawF0[m] = f2_pack(a0, a1);
        rawF1[m] = f2_pack(b0, b1);
        psum0 = f2add(psum0, rawF0[m]);
        psum1 = f2add(psum1, rawF1[m]);
    }
    #pragma unroll
    for (int off = 16; off > 0; off >>= 1) {
        psum0 = f2add(psum0, __shfl_xor_sync(0xffffffffu, psum0, off));
        psum1 = f2add(psum1, __shfl_xor_sync(0xffffffffu, psum1, off));
    }
    if ((lt & 31) == 0) {
        red[gid][0][wg] = psum0;
        red[gid][1][wg] = psum1;
    }
    // boundary raw values for cross-warp preemph
    if (lt == 31 || lt == 63) {
        int e = lt >> 5;
        #pragma unroll
        for (int m = 0; m < 8; m++) {
            sbnd[gid][e][0][m] = rawF0[m];
            sbnd[gid][e][1][m] = rawF1[m];
        }
    }
    __syncthreads();                                   // B1

    const float mcoef = 1.0f - PREEMPH;
    const f2_t invN  = f2_pack(1.0f / FRAME_LEN, 1.0f / FRAME_LEN);
    const f2_t mco   = f2_pack(mcoef, mcoef);
    const f2_t meanF0 = f2mul(f2add(red[gid][0][0], red[gid][0][1]), invN);
    const f2_t meanF1 = f2mul(f2add(red[gid][1][0], red[gid][1][1]), invN);
    const f2_t m03F0 = f2mul(meanF0, mco);
    const f2_t m03F1 = f2mul(meanF1, mco);
    const f2_t negP  = f2_pack(-PREEMPH, -PREEMPH);
    const f2_t Cp    = f2_pack(0.70710678118654752440f, 0.70710678118654752440f);

    // ---- preemph + window into packed stage-1 registers ----
    f2_t XR[8], XI[8];
    #pragma unroll
    for (int m = 0; m < 8; m++) {
        f2_t up0 = __shfl_up_sync(0xffffffffu, rawF0[m], 1);
        f2_t up1 = __shfl_up_sync(0xffffffffu, rawF1[m], 1);
        if (lt == 0)  { up0 = (m == 0) ? rawF0[0] : sbnd[gid][1][0][m - 1];
                        up1 = (m == 0) ? rawF1[0] : sbnd[gid][1][1][m - 1]; }
        if (lt == 32) { up0 = sbnd[gid][0][0][m];
                        up1 = sbnd[gid][0][1][m]; }
        int i = lt + 64 * m;
        if (i < FRAME_LEN) {
            float w = __ldg(window + i);
            f2_t Wp = f2_pack(w, w);
            XR[m] = f2mul(f2sub(f2fma(up0, negP, rawF0[m]), m03F0), Wp);
            XI[m] = f2mul(f2sub(f2fma(up1, negP, rawF1[m]), m03F1), Wp);
        } else {
            XR[m] = 0ULL; XI[m] = 0ULL;
        }
    }

    // ---- stage 1: twiddle W512^{lt*j} ----
    {
        f2_t cp[8], sp[8];
        #pragma unroll
        for (int j = 1; j < 8; j++) {
            int a = (lt * j) & 511;
            float c = __ldg(dcos + 512 + a), s = __ldg(dsin + 512 + a);
            cp[j] = f2_pack(c, c); sp[j] = f2_pack(s, s);
        }
        fft8p(XR, XI, Cp);
        #pragma unroll
        for (int j = 1; j < 8; j++) {
            f2_t t1 = f2mul(XI[j], sp[j]);
            f2_t t2 = f2mul(XR[j], sp[j]);
            f2_t rr = f2fma(XR[j], cp[j], t1);
            XI[j] = f2sub(f2mul(XI[j], cp[j]), t2);
            XR[j] = rr;
        }
    }

    // ---- exchange 1: cx[72j + lt] (first touch of cx; no barrier needed) ----
    #pragma unroll
    for (int j = 0; j < 8; j++)
        cx[gid][72 * j + lt] = make_ulonglong2(XR[j], XI[j]);
    __syncthreads();                                   // B3
    const int J = lt >> 3, v = lt & 7;
    #pragma unroll
    for (int m = 0; m < 8; m++) {
        ulonglong2 z = cx[gid][72 * J + v + 8 * m];
        XR[m] = z.x; XI[m] = z.y;
    }

    // ---- stage 2: twiddle W64^{v*i} = W512^{8vi} ----
    {
        f2_t cp[8], sp[8];
        #pragma unroll
        for (int i = 1; i < 8; i++) {
            int a = (8 * v * i) & 511;
            float c = __ldg(dcos + 512 + a), s = __ldg(dsin + 512 + a);
            cp[i] = f2_pack(c, c); sp[i] = f2_pack(s, s);
        }
        fft8p(XR, XI, Cp);
        #pragma unroll
        for (int i = 1; i < 8; i++) {
            f2_t t1 = f2mul(XI[i], sp[i]);
            f2_t t2 = f2mul(XR[i], sp[i]);
            f2_t rr = f2fma(XR[i], cp[i], t1);
            XI[i] = f2sub(f2mul(XI[i], cp[i]), t2);
            XR[i] = rr;
        }
    }

    // ---- exchange 2: cx[80J + 9i + v] (injective: 9i+v<=70<80) ----
    __syncthreads();                                   // B4
    #pragma unroll
    for (int i = 0; i < 8; i++)
        cx[gid][80 * J + 9 * i + v] = make_ulonglong2(XR[i], XI[i]);
    __syncthreads();                                   // B5
    const int I = v;
    #pragma unroll
    for (int m = 0; m < 8; m++) {
        ulonglong2 z = cx[gid][80 * J + 9 * I + m];
        XR[m] = z.x; XI[m] = z.y;
    }

    // ---- stage 3 (no twiddle). Result: X[64s + 8I + J] ----
    fft8p(XR, XI, Cp);

    // ---- natural-order store at swizzled address 72s + 9I + J ----
    __syncthreads();                                   // B6
    #pragma unroll
    for (int s = 0; s < 8; s++)
        cx[gid][72 * s + 9 * I + J] = make_ulonglong2(XR[s], XI[s]);
    __syncthreads();                                   // B7

    // ---- conjugate-symmetry split + power (packed) ----
    {
        const f2_t halfp = f2_pack(0.5f, 0.5f);
        for (int k = lt; k < NK; k += 64) {
            int n = (NFFT - k) & (NFFT - 1);
            int ak = 72 * (k >> 6) + 9 * ((k >> 3) & 7) + (k & 7);
            int an = 72 * (n >> 6) + 9 * ((n >> 3) & 7) + (n & 7);
            ulonglong2 zk = cx[gid][ak];
            ulonglong2 zn = cx[gid][an];
            f2_t Xr = f2mul(f2add(zk.x, zn.x), halfp);
            f2_t Xi = f2mul(f2sub(zk.y, zn.y), halfp);
            f2_t Yr = f2mul(f2add(zk.y, zn.y), halfp);
            f2_t Yi = f2mul(f2sub(zn.x, zk.x), halfp);
            pw2[gid][0][k] = f2fma(Xr, Xr, f2mul(Xi, Xi));
            pw2[gid][1][k] = f2fma(Yr, Yr, f2mul(Yi, Yi));
        }
    }
    __syncthreads();                                   // B8

    // ---- packed mel + log (exact support width) ----
    for (int idx = lt; idx < 2 * NMEL; idx += 64) {
        const int fr = (idx < NMEL) ? 0 : 1;
        const int m  = idx - fr * NMEL;
        const int klo = __ldg(&g_klo[m]);
        const int cnt = __ldg(&g_kcnt[m]);

        const f2_t* pk = &pw2[gid][fr][klo];
        f2_t acc = 0ULL;
        for (int j = 0; j < cnt; j++) {
            float w = __ldg(&g_wpack[j * NMEL + m]);
            acc = f2fma(pk[j], f2_pack(w, w), acc);
        }
        float a0, a1;
        f2_unpack(acc, a0, a1);

        if (val[0])
            out[(size_t)(b * NFRAMES + 2 * pc[0] + fr) * NMEL + m] = __logf(fmaxf(a0, EPS_F));
        if (val[1])
            out[(size_t)(b * NFRAMES + 2 * pc[1] + fr) * NMEL + m] = __logf(fmaxf(a1, EPS_F));
    }
}

// ================= CMN: one block per batch computes means =================
__global__ __launch_bounds__(1024)
void k_cmn_mean2(const float* __restrict__ out)
{
    __shared__ float4 sm[1020];
    const int b   = blockIdx.x;
    const int tid = threadIdx.x;
    const int lane = tid % 20;      // float4 column (80 mels / 4)
    const int s    = tid / 20;      // 0..51 (51 valid groups)

    float4 acc = make_float4(0.f, 0.f, 0.f, 0.f);
    if (s < 51) {
        for (int f = s; f < NFRAMES; f += 51) {
            float4 vv = *(const float4*)(out + ((size_t)b * NFRAMES + f) * NMEL + lane * 4);
            acc.x += vv.x; acc.y += vv.y; acc.z += vv.z; acc.w += vv.w;
        }
        sm[s * 20 + lane] = acc;
    }
    __syncthreads();
    #pragma unroll
    for (int h = 32; h > 0; h >>= 1) {
        if (s < h && s + h < 51) {
            float4 o_ = sm[(s + h) * 20 + lane];
            float4 m_ = sm[s * 20 + lane];
            m_.x += o_.x; m_.y += o_.y; m_.z += o_.z; m_.w += o_.w;
            sm[s * 20 + lane] = m_;
        }
        __syncthreads();
    }
    if (tid < 20) {
        float4 t = sm[tid];
        const float inv = 1.0f / NFRAMES;
        t.x *= inv; t.y *= inv; t.z *= inv; t.w *= inv;
        *(float4*)(g_mean + b * NMEL + tid * 4) = t;
    }
}

__global__ void k_cmn_sub(float* __restrict__ out)
{
    size_t i = (size_t)blockIdx.x * blockDim.x + threadIdx.x;
    const size_t n4 = (size_t)M_TOTAL * (NMEL / 4);
    if (i >= n4) return;
    int m4 = (int)(i % (NMEL / 4));
    int b  = (int)(i / ((size_t)NFRAMES * (NMEL / 4)));
    float4 mu = *(const float4*)(g_mean + b * NMEL + m4 * 4);
    float4 vv = *(float4*)(out + i * 4);
    vv.x -= mu.x; vv.y -= mu.y; vv.z -= mu.z; vv.w -= mu.w;
    *(float4*)(out + i * 4) = vv;
}

// ================= launch =================
extern "C" void kernel_launch(void* const* d_in, const int* in_sizes, int n_in,
                              void* d_out, int out_size)
{
    const float* wav    = (const float*)d_in[0];
    const float* window = (const float*)d_in[1];
    const float* melf   = (const float*)d_in[2];
    const float* dcos   = (const float*)d_in[3];
    const float* dsin   = (const float*)d_in[4];
    float* out = (float*)d_out;

    k_init<<<8, 256>>>(melf);
    k_fused<<<dim3((NPAIRS + 3) / 4, BATCH), 128>>>(wav, window, dcos, dsin, out);
    k_cmn_mean2<<<BATCH, 1024>>>(out);
    {
        size_t n4 = (size_t)M_TOTAL * (NMEL / 4);
        k_cmn_sub<<<dim3((unsigned)((n4 + 255) / 256)), 256>>>(out);
    }
}

// round 17
// speedup vs baseline: 1.1238x; 1.0073x over previous
#include <cuda_runtime.h>
#include <cuda_bf16.h>
#include <math.h>

// ---------------- problem constants ----------------
#define BATCH      32
#define T_SAMPLES  480000
#define FRAME_LEN  400
#define FRAME_SHIFT 160
#define NFFT       512
#define NK         257
#define NMEL       80
#define NFRAMES    2998
#define NPAIRS     (NFRAMES/2)       // 1499
#define M_TOTAL    (BATCH*NFRAMES)   // 95936
#define SCALE      32768.0f
#define PREEMPH    0.97f
#define EPS_F      1.1920928955078125e-07f
#define MAXSUP     24

// ---------------- scratch ----------------
__device__ float g_mean [BATCH * NMEL];
__device__ int   g_klo  [NMEL];
__device__ int   g_kcnt [NMEL];
__device__ float g_wpack[MAXSUP * NMEL];

// ================= f32x2 packed-math helpers =================
typedef unsigned long long f2_t;

__device__ __forceinline__ f2_t f2_pack(float lo, float hi) {
    f2_t r; asm("mov.b64 %0,{%1,%2};" : "=l"(r) : "f"(lo), "f"(hi)); return r;
}
__device__ __forceinline__ void f2_unpack(f2_t a, float& lo, float& hi) {
    asm("mov.b64 {%0,%1},%2;" : "=f"(lo), "=f"(hi) : "l"(a));
}
__device__ __forceinline__ f2_t f2add(f2_t a, f2_t b){ f2_t d; asm("add.rn.f32x2 %0,%1,%2;" : "=l"(d) : "l"(a), "l"(b)); return d; }
__device__ __forceinline__ f2_t f2sub(f2_t a, f2_t b){ f2_t d; asm("sub.rn.f32x2 %0,%1,%2;" : "=l"(d) : "l"(a), "l"(b)); return d; }
__device__ __forceinline__ f2_t f2mul(f2_t a, f2_t b){ f2_t d; asm("mul.rn.f32x2 %0,%1,%2;" : "=l"(d) : "l"(a), "l"(b)); return d; }
__device__ __forceinline__ f2_t f2fma(f2_t a, f2_t b, f2_t c){ f2_t d; asm("fma.rn.f32x2 %0,%1,%2,%3;" : "=l"(d) : "l"(a), "l"(b), "l"(c)); return d; }

// ================= init: mel support bounds + packed weights =================
__global__ void k_init(const float* __restrict__ melf)
{
    __shared__ int sklo[NMEL];
    const int t = threadIdx.x;
    if (t < NMEL) {
        double mel_lo = 1127.0 * log(1.0 + 20.0 / 700.0);
        double mel_hi = 1127.0 * log(1.0 + 8000.0 / 700.0);
        double delta  = (mel_hi - mel_lo) / (double)(NMEL + 1);
        double left   = mel_lo + t * delta;
        double right  = left + 2.0 * delta;
        double fl     = 700.0 * (exp(left  / 1127.0) - 1.0);
        double fr     = 700.0 * (exp(right / 1127.0) - 1.0);
        int klo = (int)floor(fl / 31.25) - 1;
        if (klo < 0) klo = 0;
        int khi = (int)ceil(fr / 31.25) + 1;
        if (khi > 256) khi = 256;
        int cnt = khi - klo + 1;
        if (cnt > MAXSUP) cnt = MAXSUP;
        sklo[t] = klo;
        if (blockIdx.x == 0) {
            g_klo[t]  = klo;
            g_kcnt[t] = cnt;
        }
    }
    __syncthreads();
    for (int idx = blockIdx.x * blockDim.x + t; idx < MAXSUP * NMEL;
         idx += gridDim.x * blockDim.x) {
        int j = idx / NMEL, m = idx % NMEL;
        int k = sklo[m] + j;
        g_wpack[j * NMEL + m] = (k <= 256) ? melf[(size_t)k * NMEL + m] : 0.f;
    }
}

// 8-point DFT on f32x2-packed registers
__device__ __forceinline__ void fft8p(f2_t* r, f2_t* q, f2_t Cp)
{
    f2_t t0r=f2add(r[0],r[4]), t0i=f2add(q[0],q[4]);
    f2_t t1r=f2sub(r[0],r[4]), t1i=f2sub(q[0],q[4]);
    f2_t t2r=f2add(r[2],r[6]), t2i=f2add(q[2],q[6]);
    f2_t t3r=f2sub(r[2],r[6]), t3i=f2sub(q[2],q[6]);
    f2_t e0r=f2add(t0r,t2r), e0i=f2add(t0i,t2i);
    f2_t e2r=f2sub(t0r,t2r), e2i=f2sub(t0i,t2i);
    f2_t e1r=f2add(t1r,t3i), e1i=f2sub(t1i,t3r);
    f2_t e3r=f2sub(t1r,t3i), e3i=f2add(t1i,t3r);

    f2_t s0r=f2add(r[1],r[5]), s0i=f2add(q[1],q[5]);
    f2_t s1r=f2sub(r[1],r[5]), s1i=f2sub(q[1],q[5]);
    f2_t s2r=f2add(r[3],r[7]), s2i=f2add(q[3],q[7]);
    f2_t s3r=f2sub(r[3],r[7]), s3i=f2sub(q[3],q[7]);
    f2_t o0r=f2add(s0r,s2r), o0i=f2add(s0i,s2i);
    f2_t o2r=f2sub(s0r,s2r), o2i=f2sub(s0i,s2i);
    f2_t o1r=f2add(s1r,s3i), o1i=f2sub(s1i,s3r);
    f2_t o3r=f2sub(s1r,s3i), o3i=f2add(s1i,s3r);

    f2_t u1r=f2mul(f2add(o1r,o1i),Cp);
    f2_t u1i=f2mul(f2sub(o1i,o1r),Cp);
    f2_t u3r=f2mul(f2sub(o3i,o3r),Cp);
    f2_t ct3=f2mul(f2add(o3r,o3i),Cp);   // u3i = -ct3

    r[0]=f2add(e0r,o0r); q[0]=f2add(e0i,o0i);
    r[4]=f2sub(e0r,o0r); q[4]=f2sub(e0i,o0i);
    r[1]=f2add(e1r,u1r); q[1]=f2add(e1i,u1i);
    r[5]=f2sub(e1r,u1r); q[5]=f2sub(e1i,u1i);
    r[2]=f2add(e2r,o2i); q[2]=f2sub(e2i,o2r);
    r[6]=f2sub(e2r,o2i); q[6]=f2add(e2i,o2r);
    r[3]=f2add(e3r,u3r); q[3]=f2sub(e3i,ct3);
    r[7]=f2sub(e3r,u3r); q[7]=f2add(e3i,ct3);
}

// =====================================================================
// Fused kernel: 2 groups x 64 threads; TWO frame-pairs per group packed
// in f32x2. Register-resident raw loads + shuffle preemph (no raw smem).
// min-blocks 6 caps regs at 85 to raise occupancy (probe).
// =====================================================================
__global__ __launch_bounds__(128, 6)
void k_fused(const float* __restrict__ wav,
             const float* __restrict__ window,
             const float* __restrict__ dcos,
             const float* __restrict__ dsin,
             float* __restrict__ out)
{
    __shared__ ulonglong2 cx[2][640];    // [gid]: {re-packed, im-packed}
    __shared__ f2_t pw2[2][2][264];      // [gid][fr][k] power packed over pairs
    __shared__ f2_t red[2][2][2];        // [gid][comp][warpInGroup] packed sums
    __shared__ f2_t sbnd[2][2][2][8];    // [gid][warpEnd][comp][m] boundary raw

    const int tid = threadIdx.x;
    const int gid = tid >> 6;
    const int lt  = tid & 63;
    const int wg  = (tid >> 5) & 1;
    const int b   = blockIdx.y;

    const int paBase = 4 * blockIdx.x + 2 * gid;
    bool val[2]; int pc[2];
    #pragma unroll
    for (int p = 0; p < 2; p++) {
        int pa = paBase + p;
        val[p] = (pa < NPAIRS);
        pc[p]  = val[p] ? pa : (NPAIRS - 1);
    }

    // ---- register-resident raw loads (packed over pairs) + packed sums ----
    const float* xA = wav + (size_t)b * T_SAMPLES + (size_t)(2 * pc[0]) * FRAME_SHIFT;
    const float* xB = wav + (size_t)b * T_SAMPLES + (size_t)(2 * pc[1]) * FRAME_SHIFT;
    f2_t rawF0[8], rawF1[8];
    f2_t psum0 = 0ULL, psum1 = 0ULL;
    #pragma unroll
    for (int m = 0; m < 8; m++) {
        int i = lt + 64 * m;
        float a0 = 0.f, a1 = 0.f, b0 = 0.f, b1 = 0.f;
        if (i < FRAME_LEN) {
            a0 = xA[i] * SCALE;               b0 = xA[i + FRAME_SHIFT] * SCALE;
            a1 = xB[i] * SCALE;               b1 = xB[i + FRAME_SHIFT] * SCALE;
        }
        rawF0[m] = f2_pack(a0, a1);
        rawF1[m] = f2_pack(b0, b1);
        psum0 = f2add(psum0, rawF0[m]);
        psum1 = f2add(psum1, rawF1[m]);
    }
    #pragma unroll
    for (int off = 16; off > 0; off >>= 1) {
        psum0 = f2add(psum0, __shfl_xor_sync(0xffffffffu, psum0, off));
        psum1 = f2add(psum1, __shfl_xor_sync(0xffffffffu, psum1, off));
    }
    if ((lt & 31) == 0) {
        red[gid][0][wg] = psum0;
        red[gid][1][wg] = psum1;
    }
    // boundary raw values for cross-warp preemph
    if (lt == 31 || lt == 63) {
        int e = lt >> 5;
        #pragma unroll
        for (int m = 0; m < 8; m++) {
            sbnd[gid][e][0][m] = rawF0[m];
            sbnd[gid][e][1][m] = rawF1[m];
        }
    }
    __syncthreads();                                   // B1

    const float mcoef = 1.0f - PREEMPH;
    const f2_t invN  = f2_pack(1.0f / FRAME_LEN, 1.0f / FRAME_LEN);
    const f2_t mco   = f2_pack(mcoef, mcoef);
    const f2_t meanF0 = f2mul(f2add(red[gid][0][0], red[gid][0][1]), invN);
    const f2_t meanF1 = f2mul(f2add(red[gid][1][0], red[gid][1][1]), invN);
    const f2_t m03F0 = f2mul(meanF0, mco);
    const f2_t m03F1 = f2mul(meanF1, mco);
    const f2_t negP  = f2_pack(-PREEMPH, -PREEMPH);
    const f2_t Cp    = f2_pack(0.70710678118654752440f, 0.70710678118654752440f);

    // ---- preemph + window into packed stage-1 registers ----
    f2_t XR[8], XI[8];
    #pragma unroll
    for (int m = 0; m < 8; m++) {
        f2_t up0 = __shfl_up_sync(0xffffffffu, rawF0[m], 1);
        f2_t up1 = __shfl_up_sync(0xffffffffu, rawF1[m], 1);
        if (lt == 0)  { up0 = (m == 0) ? rawF0[0] : sbnd[gid][1][0][m - 1];
                        up1 = (m == 0) ? rawF1[0] : sbnd[gid][1][1][m - 1]; }
        if (lt == 32) { up0 = sbnd[gid][0][0][m];
                        up1 = sbnd[gid][0][1][m]; }
        int i = lt + 64 * m;
        if (i < FRAME_LEN) {
            float w = __ldg(window + i);
            f2_t Wp = f2_pack(w, w);
            XR[m] = f2mul(f2sub(f2fma(up0, negP, rawF0[m]), m03F0), Wp);
            XI[m] = f2mul(f2sub(f2fma(up1, negP, rawF1[m]), m03F1), Wp);
        } else {
            XR[m] = 0ULL; XI[m] = 0ULL;
        }
    }

    // ---- stage 1: twiddle W512^{lt*j} ----
    {
        f2_t cp[8], sp[8];
        #pragma unroll
        for (int j = 1; j < 8; j++) {
            int a = (lt * j) & 511;
            float c = __ldg(dcos + 512 + a), s = __ldg(dsin + 512 + a);
            cp[j] = f2_pack(c, c); sp[j] = f2_pack(s, s);
        }
        fft8p(XR, XI, Cp);
        #pragma unroll
        for (int j = 1; j < 8; j++) {
            f2_t t1 = f2mul(XI[j], sp[j]);
            f2_t t2 = f2mul(XR[j], sp[j]);
            f2_t rr = f2fma(XR[j], cp[j], t1);
            XI[j] = f2sub(f2mul(XI[j], cp[j]), t2);
            XR[j] = rr;
        }
    }

    // ---- exchange 1: cx[72j + lt] (first touch of cx; no barrier needed) ----
    #pragma unroll
    for (int j = 0; j < 8; j++)
        cx[gid][72 * j + lt] = make_ulonglong2(XR[j], XI[j]);
    __syncthreads();                                   // B3
    const int J = lt >> 3, v = lt & 7;
    #pragma unroll
    for (int m = 0; m < 8; m++) {
        ulonglong2 z = cx[gid][72 * J + v + 8 * m];
        XR[m] = z.x; XI[m] = z.y;
    }

    // ---- stage 2: twiddle W64^{v*i} = W512^{8vi} ----
    {
        f2_t cp[8], sp[8];
        #pragma unroll
        for (int i = 1; i < 8; i++) {
            int a = (8 * v * i) & 511;
            float c = __ldg(dcos + 512 + a), s = __ldg(dsin + 512 + a);
            cp[i] = f2_pack(c, c); sp[i] = f2_pack(s, s);
        }
        fft8p(XR, XI, Cp);
        #pragma unroll
        for (int i = 1; i < 8; i++) {
            f2_t t1 = f2mul(XI[i], sp[i]);
            f2_t t2 = f2mul(XR[i], sp[i]);
            f2_t rr = f2fma(XR[i], cp[i], t1);
            XI[i] = f2sub(f2mul(XI[i], cp[i]), t2);
            XR[i] = rr;
        }
    }

    // ---- exchange 2: cx[80J + 9i + v] (injective: 9i+v<=70<80) ----
    __syncthreads();                                   // B4
    #pragma unroll
    for (int i = 0; i < 8; i++)
        cx[gid][80 * J + 9 * i + v] = make_ulonglong2(XR[i], XI[i]);
    __syncthreads();                                   // B5
    const int I = v;
    #pragma unroll
    for (int m = 0; m < 8; m++) {
        ulonglong2 z = cx[gid][80 * J + 9 * I + m];
        XR[m] = z.x; XI[m] = z.y;
    }

    // ---- stage 3 (no twiddle). Result: X[64s + 8I + J] ----
    fft8p(XR, XI, Cp);

    // ---- natural-order store at swizzled address 72s + 9I + J ----
    __syncthreads();                                   // B6
    #pragma unroll
    for (int s = 0; s < 8; s++)
        cx[gid][72 * s + 9 * I + J] = make_ulonglong2(XR[s], XI[s]);
    __syncthreads();                                   // B7

    // ---- conjugate-symmetry split + power (packed) ----
    {
        const f2_t halfp = f2_pack(0.5f, 0.5f);
        for (int k = lt; k < NK; k += 64) {
            int n = (NFFT - k) & (NFFT - 1);
            int ak = 72 * (k >> 6) + 9 * ((k >> 3) & 7) + (k & 7);
            int an = 72 * (n >> 6) + 9 * ((n >> 3) & 7) + (n & 7);
            ulonglong2 zk = cx[gid][ak];
            ulonglong2 zn = cx[gid][an];
            f2_t Xr = f2mul(f2add(zk.x, zn.x), halfp);
            f2_t Xi = f2mul(f2sub(zk.y, zn.y), halfp);
            f2_t Yr = f2mul(f2add(zk.y, zn.y), halfp);
            f2_t Yi = f2mul(f2sub(zn.x, zk.x), halfp);
            pw2[gid][0][k] = f2fma(Xr, Xr, f2mul(Xi, Xi));
            pw2[gid][1][k] = f2fma(Yr, Yr, f2mul(Yi, Yi));
        }
    }
    __syncthreads();                                   // B8

    // ---- packed mel + log (exact support width) ----
    for (int idx = lt; idx < 2 * NMEL; idx += 64) {
        const int fr = (idx < NMEL) ? 0 : 1;
        const int m  = idx - fr * NMEL;
        const int klo = __ldg(&g_klo[m]);
        const int cnt = __ldg(&g_kcnt[m]);

        const f2_t* pk = &pw2[gid][fr][klo];
        f2_t acc = 0ULL;
        for (int j = 0; j < cnt; j++) {
            float w = __ldg(&g_wpack[j * NMEL + m]);
            acc = f2fma(pk[j], f2_pack(w, w), acc);
        }
        float a0, a1;
        f2_unpack(acc, a0, a1);

        if (val[0])
            out[(size_t)(b * NFRAMES + 2 * pc[0] + fr) * NMEL + m] = __logf(fmaxf(a0, EPS_F));
        if (val[1])
            out[(size_t)(b * NFRAMES + 2 * pc[1] + fr) * NMEL + m] = __logf(fmaxf(a1, EPS_F));
    }
}

// ================= CMN: one block per batch computes means =================
__global__ __launch_bounds__(1024)
void k_cmn_mean2(const float* __restrict__ out)
{
    __shared__ float4 sm[1020];
    const int b   = blockIdx.x;
    const int tid = threadIdx.x;
    const int lane = tid % 20;      // float4 column (80 mels / 4)
    const int s    = tid / 20;      // 0..51 (51 valid groups)

    float4 acc = make_float4(0.f, 0.f, 0.f, 0.f);
    if (s < 51) {
        for (int f = s; f < NFRAMES; f += 51) {
            float4 vv = *(const float4*)(out + ((size_t)b * NFRAMES + f) * NMEL + lane * 4);
            acc.x += vv.x; acc.y += vv.y; acc.z += vv.z; acc.w += vv.w;
        }
        sm[s * 20 + lane] = acc;
    }
    __syncthreads();
    #pragma unroll
    for (int h = 32; h > 0; h >>= 1) {
        if (s < h && s + h < 51) {
            float4 o_ = sm[(s + h) * 20 + lane];
            float4 m_ = sm[s * 20 + lane];
            m_.x += o_.x; m_.y += o_.y; m_.z += o_.z; m_.w += o_.w;
            sm[s * 20 + lane] = m_;
        }
        __syncthreads();
    }
    if (tid < 20) {
        float4 t = sm[tid];
        const float inv = 1.0f / NFRAMES;
        t.x *= inv; t.y *= inv; t.z *= inv; t.w *= inv;
        *(float4*)(g_mean + b * NMEL + tid * 4) = t;
    }
}

__global__ void k_cmn_sub(float* __restrict__ out)
{
    size_t i = (size_t)blockIdx.x * blockDim.x + threadIdx.x;
    const size_t n4 = (size_t)M_TOTAL * (NMEL / 4);
    if (i >= n4) return;
    int m4 = (int)(i % (NMEL / 4));
    int b  = (int)(i / ((size_t)NFRAMES * (NMEL / 4)));
    float4 mu = *(const float4*)(g_mean + b * NMEL + m4 * 4);
    float4 vv = *(float4*)(out + i * 4);
    vv.x -= mu.x; vv.y -= mu.y; vv.z -= mu.z; vv.w -= mu.w;
    *(float4*)(out + i * 4) = vv;
}

// ================= launch =================
extern "C" void kernel_launch(void* const* d_in, const int* in_sizes, int n_in,
                              void* d_out, int out_size)
{
    const float* wav    = (const float*)d_in[0];
    const float* window = (const float*)d_in[1];
    const float* melf   = (const float*)d_in[2];
    const float* dcos   = (const float*)d_in[3];
    const float* dsin   = (const float*)d_in[4];
    float* out = (float*)d_out;

    k_init<<<8, 256>>>(melf);
    k_fused<<<dim3((NPAIRS + 3) / 4, BATCH), 128>>>(wav, window, dcos, dsin, out);
    k_cmn_mean2<<<BATCH, 1024>>>(out);
    {
        size_t n4 = (size_t)M_TOTAL * (NMEL / 4);
        k_cmn_sub<<<dim3((unsigned)((n4 + 255) / 256)), 256>>>(out);
    }
}